// round 8
// baseline (speedup 1.0000x reference)
#include <cuda_runtime.h>

// ---------------------------------------------------------------------------
// TContextGGANN_39805756899562  —  FINAL
//
// Algorithmic result (R1, re-verified every round, rel_err = 0.0 exactly):
// the reference network has an exact fixed point at zero. All four hidden
// states initialize to zeros; every message is elementwise-gated by a hidden
// state (enc * h == 0); the GRU update (1-z)*h + z*tanh(a@Wox.T + (r*h)@Woh.T)
// maps (a=0, h=0) to exactly 0 (every term multiplies an exact 0.0, no
// rounding enters); this holds across all LOOPS iterations; the final
// attention sees Q=K=V=0, so A@V = 0. The returned (h_e, h_l, h_i, h_m) are
// identically zero for any inputs — the ~2e11 FLOPs of the apparent compute
// graph are dead code. The kernel reduces to a 64 MiB zero-fill of the
// poisoned d_out.
//
// Hardware result (R2-R7): the zero-fill is bounded by the L2 write-
// acceptance ceiling, ~2970 B/cyc (~5.86 TB/s @NAT) = 192 slices x ~16 B/cyc
// — half the 6300 B/cyc load cap, and PATH-INDEPENDENT:
//   STG.128  4096 x 4/thr : 11.04-11.46 us   <- this kernel (best)
//   STG.128  8192 x 2/thr : 11.58 us
//   STG.128  1024 x 16/thr: 11.74 us
//   TMA bulk stores       : 13.54 us
//   driver memset node    : ~13.5 us
// ncu's L2=51% confirms saturation: lts__throughput counts the combined
// read+write port; a store-only kernel can occupy at most the write half.
// The dur-kernel gap (~1.7 us) is graph-replay overhead (node-type-
// independent, R5). R8 removes the bounds predicates on the exact-fit path
// (4096*256*4 == n4 for this problem) — cleanest SASS at the floor.
// ---------------------------------------------------------------------------

// Exact-fit fast path: grid covers n4 exactly, no predicates.
__global__ void __launch_bounds__(256) tcg_zero4_exact(float4* __restrict__ out) {
    int t = blockIdx.x * blockDim.x + threadIdx.x;
    int total = gridDim.x * blockDim.x;
    const float4 z = make_float4(0.0f, 0.0f, 0.0f, 0.0f);
    #pragma unroll
    for (int k = 0; k < 4; ++k)
        out[t + k * total] = z;
}

// Generic guarded path (any out_size).
__global__ void __launch_bounds__(256) tcg_zero4(float4* __restrict__ out, int n4) {
    int t = blockIdx.x * blockDim.x + threadIdx.x;
    int total = gridDim.x * blockDim.x;
    const float4 z = make_float4(0.0f, 0.0f, 0.0f, 0.0f);
    #pragma unroll
    for (int k = 0; k < 4; ++k) {
        int i = t + k * total;
        if (i < n4) out[i] = z;
    }
}

__global__ void tcg_zero_tail(float* __restrict__ out, int start, int n) {
    int i = start + blockIdx.x * blockDim.x + threadIdx.x;
    if (i < n) out[i] = 0.0f;
}

extern "C" void kernel_launch(void* const* d_in, const int* in_sizes, int n_in,
                              void* d_out, int out_size) {
    (void)d_in; (void)in_sizes; (void)n_in;

    float* out = (float*)d_out;
    int n  = out_size;            // 16,777,216 fp32 for this problem
    int n4 = n >> 2;              // float4 chunks; d_out is 256B-aligned
    int rem_start = n4 << 2;

    const int threads = 256;
    const int per_thread = 4;
    const int chunk = threads * per_thread;   // 1024 float4 per block

    if (n4 > 0) {
        int blocks = (n4 + chunk - 1) / chunk;
        if (n4 % chunk == 0) {
            // Exact fit (this problem: 4096 blocks) — predicate-free stores.
            tcg_zero4_exact<<<blocks, threads>>>((float4*)out);
        } else {
            tcg_zero4<<<blocks, threads>>>((float4*)out, n4);
        }
    }
    if (rem_start < n) {          // never launched for n % 4 == 0
        int rem = n - rem_start;
        int blocks = (rem + 127) / 128;
        tcg_zero_tail<<<blocks, 128>>>(out, rem_start, n);
    }
}

// round 9
// speedup vs baseline: 1.0226x; 1.0226x over previous
#include <cuda_runtime.h>

// ---------------------------------------------------------------------------
// TContextGGANN_39805756899562  —  FINAL (committed)
//
// Algorithmic result (R1, re-verified through R8, rel_err = 0.0 exactly):
// the reference network has an exact fixed point at zero. All four hidden
// states initialize to zeros; every message is elementwise-gated by a hidden
// state (enc * h == 0); the GRU update (1-z)*h + z*tanh(a@Wox.T + (r*h)@Woh.T)
// maps (a=0, h=0) to exactly 0 (every term multiplies an exact 0.0, no
// rounding enters); this holds across all LOOPS iterations; the final
// attention sees Q=K=V=0, so A@V = 0. The returned (h_e, h_l, h_i, h_m) are
// identically zero for any inputs — the ~2e11 FLOPs of the apparent compute
// graph are dead code. The kernel reduces to a 64 MiB zero-fill of the
// poisoned d_out.
//
// Hardware result (R2-R8): the zero-fill is bounded by the L2 write-
// acceptance ceiling, ~2970 B/cyc (~5.86 TB/s @NAT) = 192 slices x ~16 B/cyc
// — half the 6300 B/cyc load cap, and PATH-INDEPENDENT:
//   STG.128  4096 x 4/thr (guarded) : 11.04-11.46 us  <- this kernel (best)
//   STG.128  4096 x 4/thr (exact)   : 11.39 us (predicates are free)
//   STG.128  8192 x 2/thr           : 11.58 us
//   STG.128  1024 x 16/thr          : 11.74 us
//   TMA bulk stores                 : 13.54 us
//   driver memset node              : ~13.5 us
// ncu L2~50% = the write half of the combined LTS read+write port fully
// saturated. dur-kernel gap (~1.6 us) is graph-replay overhead, node-type-
// independent (R5). Grid shape, unroll depth, predication, and write path
// are all flat at this floor — no further optimization exists.
// ---------------------------------------------------------------------------

__global__ void __launch_bounds__(256) tcg_zero4(float4* __restrict__ out, int n4) {
    int t = blockIdx.x * blockDim.x + threadIdx.x;
    int total = gridDim.x * blockDim.x;
    const float4 z = make_float4(0.0f, 0.0f, 0.0f, 0.0f);
    // 4 coalesced STG.128 per thread; fully unrolled, predicated bounds
    // (predicates measured free at issue ~11%).
    #pragma unroll
    for (int k = 0; k < 4; ++k) {
        int i = t + k * total;
        if (i < n4) out[i] = z;
    }
}

__global__ void tcg_zero_tail(float* __restrict__ out, int start, int n) {
    int i = start + blockIdx.x * blockDim.x + threadIdx.x;
    if (i < n) out[i] = 0.0f;
}

extern "C" void kernel_launch(void* const* d_in, const int* in_sizes, int n_in,
                              void* d_out, int out_size) {
    (void)d_in; (void)in_sizes; (void)n_in;

    float* out = (float*)d_out;
    int n  = out_size;            // 16,777,216 fp32 for this problem
    int n4 = n >> 2;              // float4 chunks; d_out is 256B-aligned
    int rem_start = n4 << 2;

    if (n4 > 0) {
        const int threads = 256;
        const int per_thread = 4;
        int blocks = (n4 + threads * per_thread - 1) / (threads * per_thread);
        tcg_zero4<<<blocks, threads>>>((float4*)out, n4);   // 4096 blocks here
    }
    if (rem_start < n) {          // never launched for n % 4 == 0
        int rem = n - rem_start;
        int blocks = (rem + 127) / 128;
        tcg_zero_tail<<<blocks, 128>>>(out, rem_start, n);
    }
}